// round 3
// baseline (speedup 1.0000x reference)
#include <cuda_runtime.h>
#include <cstdint>

// Problem shape (fixed by the dataset)
#define BATCH   8
#define SEQ     4096
#define CHANS   1024

// Tiling: block = 8 warps; each warp = 32 lanes x float4 = 128 channels, 8 rows
#define CG      128                  // channels per block
#define ROWS_W  8                    // timesteps per thread
#define WARPS   8
#define CHUNK_T (ROWS_W * WARPS)     // 64 timesteps per block
#define NCHUNK  (SEQ / CHUNK_T)      // 64
#define CGRP    (CHANS / CG)         // 8
#define L4      (CG / 4)             // 32 float4 lanes per row

// Lookback state: one flag per (b, cgroup, chunk) + float4 value arrays.
// flag: 0 = invalid, 1 = aggregate valid, 2 = inclusive valid
#define NFLAG (BATCH * CGRP * NCHUNK)
__device__ int    g_flag[NFLAG];
__device__ float4 g_agg [NFLAG * L4];
__device__ float4 g_inc [NFLAG * L4];

__global__ void init_flags_kernel() {
    int i = blockIdx.x * blockDim.x + threadIdx.x;
    if (i < NFLAG) g_flag[i] = 0;
}

__device__ __forceinline__ int ld_acquire_gpu(const int* p) {
    int v;
    asm volatile("ld.global.acquire.gpu.b32 %0, [%1];" : "=r"(v) : "l"(p) : "memory");
    return v;
}
__device__ __forceinline__ void st_release_gpu(int* p, int v) {
    asm volatile("st.global.release.gpu.b32 [%0], %1;" :: "l"(p), "r"(v) : "memory");
}
__device__ __forceinline__ void fence_acq_rel_gpu() {
    asm volatile("fence.acq_rel.gpu;" ::: "memory");
}

__device__ __forceinline__ float4 f4_fma(float4 a, float4 b, float4 c) {
    float4 r;
    r.x = fmaf(a.x, b.x, c.x); r.y = fmaf(a.y, b.y, c.y);
    r.z = fmaf(a.z, b.z, c.z); r.w = fmaf(a.w, b.w, c.w);
    return r;
}
__device__ __forceinline__ float4 f4_mul(float4 a, float4 b) {
    return make_float4(a.x*b.x, a.y*b.y, a.z*b.z, a.w*b.w);
}

__global__ __launch_bounds__(256, 4)
void scan_kernel(const float4* __restrict__ x, const float4* __restrict__ d,
                 float4* __restrict__ y) {
    __shared__ float4 sub_b[WARPS][L4];   // per-warp aggregates
    __shared__ float4 seed [WARPS][L4];   // per-warp starting y

    const int cg   = blockIdx.x;          // channel group
    const int b    = blockIdx.y;          // batch
    const int k    = blockIdx.z;          // chunk (slowest -> in-order block ids)
    const int tid  = threadIdx.x;
    const int lane = tid & 31;            // float4 column within group
    const int w    = tid >> 5;            // warp id == row-slab id

    const int col = cg * L4 + lane;       // global float4 column
    const float4 dv = d[col];

    const size_t rowstride = CHANS / 4;   // 256 float4 per row
    const size_t base = ((size_t)b * SEQ + (size_t)k * CHUNK_T + (size_t)w * ROWS_W) * rowstride + col;
    const float4* xb = x + base;
    float4*       yb = y + base;

    // ---- Load 8 rows into registers + local aggregate ----
    float4 xr[ROWS_W];
    float4 Bv = make_float4(0.f, 0.f, 0.f, 0.f);
    #pragma unroll
    for (int i = 0; i < ROWS_W; i++) {
        xr[i] = xb[(size_t)i * rowstride];
        Bv = f4_fma(dv, Bv, xr[i]);
    }
    sub_b[w][lane] = Bv;
    __syncthreads();

    // ---- Warp 0: combine warp aggregates, publish, lookback, seeds ----
    if (tid < 32) {
        float4 d2  = f4_mul(dv, dv);
        float4 d4  = f4_mul(d2, d2);
        float4 d8  = f4_mul(d4, d4);
        float4 d16 = f4_mul(d8, d8);
        float4 d32 = f4_mul(d16, d16);
        float4 d64 = f4_mul(d32, d32);

        // Sequential combine across the 8 warp slabs (factor d^8)
        float4 B = make_float4(0.f, 0.f, 0.f, 0.f);
        #pragma unroll
        for (int s = 0; s < WARPS; s++) {
            seed[s][lane] = B;            // exclusive, pre-carry
            B = f4_fma(d8, B, sub_b[s][lane]);
        }

        const int fbase = (b * CGRP + cg) * NCHUNK;   // flag/value base for this chain
        const int fidx  = fbase + k;
        float4 carry = make_float4(0.f, 0.f, 0.f, 0.f);

        if (k == 0) {
            __stcg(&g_inc[fidx * L4 + lane], B);
            st_release_gpu(&g_flag[fidx], 2);   // release: all lanes' stcg... see note
            // NOTE: release is per-thread; ensure warp-wide: every lane does its own
            // value store; only lane 0 writes the flag -> need cross-lane ordering.
        } else {
            __stcg(&g_agg[fidx * L4 + lane], B);
            st_release_gpu(&g_flag[fidx], 1);
        }
        // Cross-lane ordering fix: each lane released its OWN flag-store above would
        // be wrong (32 flag writes). Instead: we do value store (stcg) in every lane,
        // then a warp sync + one release store by lane 0 after an acq_rel fence.
        // To keep it simple and correct, we redo flag publication properly below.
        __syncwarp();

        if (k > 0) {
            // ---- Warp-parallel window lookback ----
            int woff = 0;                 // window offset (distance of window start)
            float4 factor = make_float4(1.f, 1.f, 1.f, 1.f);
            for (;;) {
                const int avail = k - woff;           // predecessors not yet consumed
                int D; int full_window;
                // Poll: lane L watches predecessor at distance woff+L
                const int j_lane = k - 1 - woff - lane;
                int spin = 0;
                for (;;) {
                    int f = (lane < avail) ? ld_acquire_gpu(&g_flag[fbase + j_lane]) : 1;
                    unsigned m2 = __ballot_sync(0xffffffffu, (lane < avail) && (f == 2));
                    unsigned m1 = __ballot_sync(0xffffffffu, f >= 1);
                    if (m2) {
                        D = __ffs(m2) - 1;
                        if ((((1u << D) - 1u) & ~m1) == 0u) { full_window = 0; break; }
                    } else if (avail > 32 && m1 == 0xffffffffu) {
                        full_window = 1; D = 31; break;
                    }
                    if (++spin > 4) __nanosleep(40);
                }
                fence_acq_rel_gpu();   // order value loads below after observed flags

                // Consume distances woff .. woff+D (inclusive value at D unless full window)
                const int n = D + 1;
                // depth-2 pipelined value loads
                float4 v = __ldcg(((!full_window && 0 == D) ? g_inc : g_agg)
                                  + (size_t)(fbase + k - 1 - woff) * L4 + lane);
                for (int L = 0; L < n; L++) {
                    float4 vn;
                    if (L + 1 < n) {
                        const float4* src = (!full_window && (L + 1 == D)) ? g_inc : g_agg;
                        vn = __ldcg(src + (size_t)(fbase + k - 1 - woff - (L + 1)) * L4 + lane);
                    }
                    carry = f4_fma(factor, v, carry);
                    factor = f4_mul(factor, d64);
                    v = vn;
                }
                if (!full_window) break;
                woff += 32;
            }
            // Publish inclusive: value stores by all lanes, then one release flag store.
            float4 inc = f4_fma(d64, carry, B);
            __stcg(&g_inc[fidx * L4 + lane], inc);
            fence_acq_rel_gpu();                 // make all lanes' value stores visible
            __syncwarp();
            if (lane == 0) st_release_gpu(&g_flag[fidx], 2);
        }

        // seed[s] = d^{8 s} * carry + exclusive_prefix(s)
        float4 p = make_float4(1.f, 1.f, 1.f, 1.f);
        #pragma unroll
        for (int s = 0; s < WARPS; s++) {
            float4 e = seed[s][lane];
            seed[s][lane] = f4_fma(p, carry, e);
            p = f4_mul(p, d8);
        }
    }
    __syncthreads();

    // ---- Apply: seeded recurrence over register-resident rows, float4 stores ----
    float4 yv = seed[w][lane];
    #pragma unroll
    for (int i = 0; i < ROWS_W; i++) {
        yv = f4_fma(dv, yv, xr[i]);
        yb[(size_t)i * rowstride] = yv;
    }
}

extern "C" void kernel_launch(void* const* d_in, const int* in_sizes, int n_in,
                              void* d_out, int out_size) {
    const float4* x = (const float4*)d_in[0];
    const float4* d = (const float4*)d_in[1];
    float4* y = (float4*)d_out;
    (void)in_sizes; (void)n_in; (void)out_size;

    init_flags_kernel<<<(NFLAG + 255) / 256, 256>>>();

    dim3 grid(CGRP, BATCH, NCHUNK);   // chunk on z: predecessors have smaller linear ids
    scan_kernel<<<grid, 256>>>(x, d, y);
}

// round 4
// speedup vs baseline: 1.3068x; 1.3068x over previous
#include <cuda_runtime.h>
#include <cstdint>

// Problem shape
#define BATCH   8
#define SEQ     4096
#define CHANS   1024

// Geometry: block = one super-chunk = 64 rows x 128 channels
#define WARPS   8                    // warps per block; warp w = local chunk w
#define ROWS_W  8                    // rows per warp (per thread)
#define SUPER_T (WARPS * ROWS_W)     // 64 rows per block
#define NSUP    (SEQ / SUPER_T)      // 64 supers along t
#define L4      32                   // float4 lanes per warp => 128 channels
#define CGRP    (CHANS / (L4 * 4))   // 8 channel groups
#define NCHAIN  (BATCH * CGRP)       // 64 independent chains
#define RS      (CHANS / 4)          // row stride in float4 = 256

// Published per-super aggregates + ready flags (cleared each launch)
__device__ float4 g_sa  [NCHAIN][NSUP][L4];
__device__ int    g_flag[NCHAIN][NSUP];

__global__ void init_flags_kernel() {
    int i = blockIdx.x * blockDim.x + threadIdx.x;
    if (i < NCHAIN * NSUP) ((int*)g_flag)[i] = 0;
}

__device__ __forceinline__ int ld_acquire_gpu(const int* p) {
    int v;
    asm volatile("ld.global.acquire.gpu.b32 %0, [%1];" : "=r"(v) : "l"(p) : "memory");
    return v;
}
__device__ __forceinline__ void st_release_gpu(int* p, int v) {
    asm volatile("st.global.release.gpu.b32 [%0], %1;" :: "l"(p), "r"(v) : "memory");
}

__device__ __forceinline__ float4 f4_fma(float4 a, float4 b, float4 c) {
    float4 r;
    r.x = fmaf(a.x, b.x, c.x); r.y = fmaf(a.y, b.y, c.y);
    r.z = fmaf(a.z, b.z, c.z); r.w = fmaf(a.w, b.w, c.w);
    return r;
}
__device__ __forceinline__ float4 f4_mul(float4 a, float4 b) {
    return make_float4(a.x*b.x, a.y*b.y, a.z*b.z, a.w*b.w);
}

__global__ __launch_bounds__(256)
void scan_kernel(const float4* __restrict__ x, const float4* __restrict__ d,
                 float4* __restrict__ y) {
    __shared__ float4 sB[WARPS][L4];   // per-warp local chunk aggregates
    __shared__ float4 sC[L4];          // super-exclusive prefix (value before this super)

    const int cg   = blockIdx.x;       // channel group (0..7)
    const int b    = blockIdx.y;       // batch
    const int s    = blockIdx.z;       // super index (slowest -> in-order ids)
    const int tid  = threadIdx.x;
    const int lane = tid & 31;
    const int w    = tid >> 5;         // warp id == local chunk

    const int col   = cg * L4 + lane;  // global float4 column
    const int chain = b * CGRP + cg;
    const float4 dv = d[col];

    const size_t row0 = (size_t)b * SEQ + (size_t)s * SUPER_T + (size_t)w * ROWS_W;
    const float4* xp = x + row0 * RS + col;
    float4*       yp = y + row0 * RS + col;

    // ---- Pass 1: load 8 rows into registers, local aggregate (chunk value B) ----
    float4 xr[ROWS_W];
    float4 Bv = make_float4(0.f, 0.f, 0.f, 0.f);
    #pragma unroll
    for (int i = 0; i < ROWS_W; i++) {
        xr[i] = __ldcs(&xp[(size_t)i * RS]);
        Bv = f4_fma(dv, Bv, xr[i]);
    }

    const float4 d2 = f4_mul(dv, dv);
    const float4 d4 = f4_mul(d2, d2);
    const float4 d8 = f4_mul(d4, d4);

    sB[w][lane] = Bv;
    __syncthreads();

    // ---- Warp 7: publish this super's self-contained aggregate ----
    if (w == 7) {
        float4 SA = make_float4(0.f, 0.f, 0.f, 0.f);
        #pragma unroll
        for (int i = 0; i < WARPS; i++)
            SA = f4_fma(d8, SA, sB[i][lane]);
        __stcg(&g_sa[chain][s][lane], SA);
        __syncwarp();
        if (lane == 0) st_release_gpu(&g_flag[chain][s], 1);
    }

    // ---- Warp 0: gather all predecessor aggregates -> super prefix C_s ----
    if (w == 0) {
        float4 C = make_float4(0.f, 0.f, 0.f, 0.f);
        if (s > 0) {
            // Lane-parallel flag poll: lane L watches supers L and L+32
            const int t1 = lane, t2 = lane + 32;
            for (;;) {
                int ok1 = (t1 >= s) ? 1 : ld_acquire_gpu(&g_flag[chain][t1]);
                int ok2 = (t2 >= s) ? 1 : ld_acquire_gpu(&g_flag[chain][t2]);
                if (__all_sync(0xffffffffu, ok1 && ok2)) break;
                __nanosleep(30);
            }
            __syncwarp();   // propagate acquire observations warp-wide

            const float4 d16 = f4_mul(d8, d8);
            const float4 d32 = f4_mul(d16, d16);
            const float4 d64 = f4_mul(d32, d32);

            // C = sum_{t<s} d64^{s-1-t} * SA_t  (ascending t => running fma)
            int t = 0;
            for (; t + 4 <= s; t += 4) {
                float4 v0 = __ldcg(&g_sa[chain][t + 0][lane]);
                float4 v1 = __ldcg(&g_sa[chain][t + 1][lane]);
                float4 v2 = __ldcg(&g_sa[chain][t + 2][lane]);
                float4 v3 = __ldcg(&g_sa[chain][t + 3][lane]);
                C = f4_fma(d64, C, v0);
                C = f4_fma(d64, C, v1);
                C = f4_fma(d64, C, v2);
                C = f4_fma(d64, C, v3);
            }
            for (; t < s; t++)
                C = f4_fma(d64, C, __ldcg(&g_sa[chain][t][lane]));
        }
        sC[lane] = C;
    }
    __syncthreads();

    // ---- Seed for this warp: E = d8^w * C + sum_{i<w} d8^{w-1-i} B_i ----
    float4 E = sC[lane];
    for (int i = 0; i < w; i++)
        E = f4_fma(d8, E, sB[i][lane]);

    // ---- Apply: seeded recurrence, streaming stores ----
    float4 yv = E;
    #pragma unroll
    for (int i = 0; i < ROWS_W; i++) {
        yv = f4_fma(dv, yv, xr[i]);
        __stcs(&yp[(size_t)i * RS], yv);
    }
}

extern "C" void kernel_launch(void* const* d_in, const int* in_sizes, int n_in,
                              void* d_out, int out_size) {
    const float4* x = (const float4*)d_in[0];
    const float4* d = (const float4*)d_in[1];
    float4* y = (float4*)d_out;
    (void)in_sizes; (void)n_in; (void)out_size;

    init_flags_kernel<<<(NCHAIN * NSUP + 255) / 256, 256>>>();

    dim3 grid(CGRP, BATCH, NSUP);   // super on z: predecessors have smaller ids
    scan_kernel<<<grid, 256>>>(x, d, y);
}

// round 5
// speedup vs baseline: 1.3226x; 1.0121x over previous
#include <cuda_runtime.h>
#include <cstdint>

// Problem shape
#define BATCH   8
#define SEQ     4096
#define CHANS   1024

// Geometry: block = one super-chunk = 128 rows x 128 channels, smem-staged
#define WARPS   8
#define ROWS_W  16                   // rows per warp (per thread)
#define SUPER_T (WARPS * ROWS_W)     // 128 rows per block
#define NSUP    (SEQ / SUPER_T)      // 32 supers along t
#define L4      32                   // float4 lanes per warp => 128 channels
#define CGRP    (CHANS / (L4 * 4))   // 8 channel groups
#define NCHAIN  (BATCH * CGRP)       // 64 independent chains
#define RS      (CHANS / 4)          // row stride in float4 = 256

// Published per-super aggregates + ready flags
__device__ float4 g_sa  [NCHAIN][NSUP][L4];
__device__ int    g_flag[NCHAIN][NSUP];

__global__ void init_flags_kernel() {
    int i = blockIdx.x * blockDim.x + threadIdx.x;
    if (i < NCHAIN * NSUP) ((int*)g_flag)[i] = 0;
}

__device__ __forceinline__ int ld_acquire_gpu(const int* p) {
    int v;
    asm volatile("ld.global.acquire.gpu.b32 %0, [%1];" : "=r"(v) : "l"(p) : "memory");
    return v;
}
__device__ __forceinline__ void st_release_gpu(int* p, int v) {
    asm volatile("st.global.release.gpu.b32 [%0], %1;" :: "l"(p), "r"(v) : "memory");
}

__device__ __forceinline__ float4 f4_fma(float4 a, float4 b, float4 c) {
    float4 r;
    r.x = fmaf(a.x, b.x, c.x); r.y = fmaf(a.y, b.y, c.y);
    r.z = fmaf(a.z, b.z, c.z); r.w = fmaf(a.w, b.w, c.w);
    return r;
}
__device__ __forceinline__ float4 f4_mul(float4 a, float4 b) {
    return make_float4(a.x*b.x, a.y*b.y, a.z*b.z, a.w*b.w);
}

// Dynamic smem layout: tile[SUPER_T][L4] | sB[WARPS][L4] | sC[L4]
#define SM_TILE   0
#define SM_SB     (SUPER_T * L4)
#define SM_SC     (SM_SB + WARPS * L4)
#define SM_COUNT  (SM_SC + L4)
#define SM_BYTES  (SM_COUNT * sizeof(float4))

__global__ __launch_bounds__(256)
void scan_kernel(const float4* __restrict__ x, const float4* __restrict__ d,
                 float4* __restrict__ y) {
    extern __shared__ float4 sm[];
    float4* tile = sm + SM_TILE;
    float4* sB   = sm + SM_SB;      // [WARPS][L4]
    float4* sC   = sm + SM_SC;      // [L4]

    const int cg   = blockIdx.x;
    const int b    = blockIdx.y;
    const int s    = blockIdx.z;     // super index (slowest -> in-order ids)
    const int tid  = threadIdx.x;
    const int lane = tid & 31;
    const int w    = tid >> 5;

    const int col   = cg * L4 + lane;
    const int chain = b * CGRP + cg;
    const float4 dv = d[col];

    const size_t row0 = (size_t)b * SEQ + (size_t)s * SUPER_T + (size_t)w * ROWS_W;
    const float4* xp = x + row0 * RS + col;
    float4*       yp = y + row0 * RS + col;
    float4* trow = tile + (w * ROWS_W) * L4 + lane;

    // ---- Pass 1: stream 16 rows -> smem, local aggregate in flight ----
    float4 Bv = make_float4(0.f, 0.f, 0.f, 0.f);
    #pragma unroll
    for (int i = 0; i < ROWS_W; i++) {
        float4 v = __ldcs(&xp[(size_t)i * RS]);
        trow[i * L4] = v;
        Bv = f4_fma(dv, Bv, v);
    }
    sB[w * L4 + lane] = Bv;
    __syncthreads();

    const float4 d2  = f4_mul(dv, dv);
    const float4 d4  = f4_mul(d2, d2);
    const float4 d8  = f4_mul(d4, d4);
    const float4 d16 = f4_mul(d8, d8);

    // ---- Warp 7: publish this super's self-contained aggregate ----
    if (w == 7) {
        float4 SA = make_float4(0.f, 0.f, 0.f, 0.f);
        #pragma unroll
        for (int i = 0; i < WARPS; i++)
            SA = f4_fma(d16, SA, sB[i * L4 + lane]);
        __stcg(&g_sa[chain][s][lane], SA);
        __syncwarp();
        if (lane == 0) st_release_gpu(&g_flag[chain][s], 1);
    }

    // ---- Warp 0: gather predecessor aggregates -> super-exclusive prefix C ----
    if (w == 0) {
        float4 C = make_float4(0.f, 0.f, 0.f, 0.f);
        if (s > 0) {
            // lane L watches flag of super L (L < s)
            for (;;) {
                int ok = (lane < s) ? ld_acquire_gpu(&g_flag[chain][lane]) : 1;
                if (__all_sync(0xffffffffu, ok)) break;
                __nanosleep(20);
            }
            __syncwarp();

            const float4 d32  = f4_mul(d16, d16);
            const float4 d64  = f4_mul(d32, d32);
            const float4 d128 = f4_mul(d64, d64);

            int t = 0;
            for (; t + 4 <= s; t += 4) {
                float4 v0 = __ldcg(&g_sa[chain][t + 0][lane]);
                float4 v1 = __ldcg(&g_sa[chain][t + 1][lane]);
                float4 v2 = __ldcg(&g_sa[chain][t + 2][lane]);
                float4 v3 = __ldcg(&g_sa[chain][t + 3][lane]);
                C = f4_fma(d128, C, v0);
                C = f4_fma(d128, C, v1);
                C = f4_fma(d128, C, v2);
                C = f4_fma(d128, C, v3);
            }
            for (; t < s; t++)
                C = f4_fma(d128, C, __ldcg(&g_sa[chain][t][lane]));
        }
        sC[lane] = C;
    }
    __syncthreads();

    // ---- Seed for this warp: E = d16^w * C + sum_{i<w} d16^{w-1-i} B_i ----
    float4 E = sC[lane];
    for (int i = 0; i < w; i++)
        E = f4_fma(d16, E, sB[i * L4 + lane]);

    // ---- Apply: seeded recurrence from smem, streaming stores ----
    float4 yv = E;
    #pragma unroll
    for (int i = 0; i < ROWS_W; i++) {
        yv = f4_fma(dv, yv, trow[i * L4]);
        __stcs(&yp[(size_t)i * RS], yv);
    }
}

extern "C" void kernel_launch(void* const* d_in, const int* in_sizes, int n_in,
                              void* d_out, int out_size) {
    const float4* x = (const float4*)d_in[0];
    const float4* d = (const float4*)d_in[1];
    float4* y = (float4*)d_out;
    (void)in_sizes; (void)n_in; (void)out_size;

    cudaFuncSetAttribute(scan_kernel, cudaFuncAttributeMaxDynamicSharedMemorySize,
                         (int)SM_BYTES);

    init_flags_kernel<<<(NCHAIN * NSUP + 255) / 256, 256>>>();

    dim3 grid(CGRP, BATCH, NSUP);   // super on z: predecessors have smaller ids
    scan_kernel<<<grid, 256, SM_BYTES>>>(x, d, y);
}

// round 6
// speedup vs baseline: 1.3596x; 1.0280x over previous
#include <cuda_runtime.h>
#include <cstdint>

// Problem shape
#define BATCH   8
#define SEQ     4096
#define CHANS   1024

// Geometry: block = one super-chunk = 128 rows x 128 channels, smem-staged.
// 8 load warps + 1 scan warp (decoupled prefix gather).
#define LWARPS  8
#define THREADS (LWARPS * 32 + 32)   // 288
#define ROWS_W  16                   // rows per load warp (per thread)
#define SUPER_T (LWARPS * ROWS_W)    // 128 rows per block
#define NSUP    (SEQ / SUPER_T)      // 32 supers along t
#define L4      32                   // float4 lanes per warp => 128 channels
#define CGRP    (CHANS / (L4 * 4))   // 8 channel groups
#define NCHAIN  (BATCH * CGRP)       // 64 independent chains
#define RS      (CHANS / 4)          // row stride in float4 = 256

// Published per-super aggregates + ready flags
__device__ float4 g_sa  [NCHAIN][NSUP][L4];
__device__ int    g_flag[NCHAIN][NSUP];

__global__ void init_flags_kernel() {
    int i = blockIdx.x * blockDim.x + threadIdx.x;
    if (i < NCHAIN * NSUP) ((int*)g_flag)[i] = 0;
}

__device__ __forceinline__ int ld_acquire_gpu(const int* p) {
    int v;
    asm volatile("ld.global.acquire.gpu.b32 %0, [%1];" : "=r"(v) : "l"(p) : "memory");
    return v;
}
__device__ __forceinline__ void st_release_gpu(int* p, int v) {
    asm volatile("st.global.release.gpu.b32 [%0], %1;" :: "l"(p), "r"(v) : "memory");
}

__device__ __forceinline__ float4 f4_fma(float4 a, float4 b, float4 c) {
    float4 r;
    r.x = fmaf(a.x, b.x, c.x); r.y = fmaf(a.y, b.y, c.y);
    r.z = fmaf(a.z, b.z, c.z); r.w = fmaf(a.w, b.w, c.w);
    return r;
}
__device__ __forceinline__ float4 f4_mul(float4 a, float4 b) {
    return make_float4(a.x*b.x, a.y*b.y, a.z*b.z, a.w*b.w);
}

// Dynamic smem layout: tile[SUPER_T][L4] | sB[LWARPS][L4] | sC[L4]
#define SM_TILE   0
#define SM_SB     (SUPER_T * L4)
#define SM_SC     (SM_SB + LWARPS * L4)
#define SM_COUNT  (SM_SC + L4)
#define SM_BYTES  (SM_COUNT * sizeof(float4))

__global__ __launch_bounds__(THREADS)
void scan_kernel(const float4* __restrict__ x, const float4* __restrict__ d,
                 float4* __restrict__ y) {
    extern __shared__ float4 sm[];
    float4* tile = sm + SM_TILE;
    float4* sB   = sm + SM_SB;      // [LWARPS][L4]
    float4* sC   = sm + SM_SC;      // [L4]

    const int cg   = blockIdx.x;
    const int b    = blockIdx.y;
    const int s    = blockIdx.z;     // super index (slowest -> in-order ids)
    const int tid  = threadIdx.x;
    const int lane = tid & 31;
    const int w    = tid >> 5;       // 0..7 load warps, 8 = scan warp

    const int col   = cg * L4 + lane;
    const int chain = b * CGRP + cg;
    const float4 dv = d[col];

    const float4 d2  = f4_mul(dv, dv);
    const float4 d4  = f4_mul(d2, d2);
    const float4 d8  = f4_mul(d4, d4);
    const float4 d16 = f4_mul(d8, d8);

    if (w < LWARPS) {
        // ---- Load warps: stream 16 rows -> smem, local aggregate in flight ----
        const size_t row0 = (size_t)b * SEQ + (size_t)s * SUPER_T + (size_t)w * ROWS_W;
        const float4* xp = x + row0 * RS + col;
        float4* trow = tile + (w * ROWS_W) * L4 + lane;

        float4 Bv = make_float4(0.f, 0.f, 0.f, 0.f);
        #pragma unroll
        for (int i = 0; i < ROWS_W; i++) {
            float4 v = __ldcs(&xp[(size_t)i * RS]);
            trow[i * L4] = v;
            Bv = f4_fma(dv, Bv, v);
        }
        sB[w * L4 + lane] = Bv;

        // Sync only the 8 load warps, then publish SA as early as possible
        asm volatile("bar.sync 1, %0;" :: "n"(LWARPS * 32) : "memory");

        if (w == 0) {
            float4 SA = make_float4(0.f, 0.f, 0.f, 0.f);
            #pragma unroll
            for (int i = 0; i < LWARPS; i++)
                SA = f4_fma(d16, SA, sB[i * L4 + lane]);
            __stcg(&g_sa[chain][s][lane], SA);
            __syncwarp();
            if (lane == 0) st_release_gpu(&g_flag[chain][s], 1);
        }
    } else {
        // ---- Scan warp: poll + gather predecessors concurrently with loads ----
        float4 C = make_float4(0.f, 0.f, 0.f, 0.f);
        if (s > 0) {
            for (;;) {
                int ok = (lane < s) ? ld_acquire_gpu(&g_flag[chain][lane]) : 1;
                if (__all_sync(0xffffffffu, ok)) break;
                __nanosleep(20);
            }
            __syncwarp();

            const float4 d32  = f4_mul(d16, d16);
            const float4 d64  = f4_mul(d32, d32);
            const float4 d128 = f4_mul(d64, d64);

            // C = sum_{t<s} d128^{s-1-t} * SA_t (ascending t => running fma)
            int t = 0;
            for (; t + 4 <= s; t += 4) {
                float4 v0 = __ldcg(&g_sa[chain][t + 0][lane]);
                float4 v1 = __ldcg(&g_sa[chain][t + 1][lane]);
                float4 v2 = __ldcg(&g_sa[chain][t + 2][lane]);
                float4 v3 = __ldcg(&g_sa[chain][t + 3][lane]);
                C = f4_fma(d128, C, v0);
                C = f4_fma(d128, C, v1);
                C = f4_fma(d128, C, v2);
                C = f4_fma(d128, C, v3);
            }
            for (; t < s; t++)
                C = f4_fma(d128, C, __ldcg(&g_sa[chain][t][lane]));
        }
        sC[lane] = C;
    }

    __syncthreads();   // join: sC ready, sB ready

    if (w < LWARPS) {
        // ---- Seed: E = d16^w * C + sum_{i<w} d16^{w-1-i} B_i ----
        float4 E = sC[lane];
        for (int i = 0; i < w; i++)
            E = f4_fma(d16, E, sB[i * L4 + lane]);

        // ---- Apply: seeded recurrence from smem, streaming stores ----
        const size_t row0 = (size_t)b * SEQ + (size_t)s * SUPER_T + (size_t)w * ROWS_W;
        float4* yp = y + row0 * RS + col;
        float4* trow = tile + (w * ROWS_W) * L4 + lane;

        float4 yv = E;
        #pragma unroll
        for (int i = 0; i < ROWS_W; i++) {
            yv = f4_fma(dv, yv, trow[i * L4]);
            __stcs(&yp[(size_t)i * RS], yv);
        }
    }
}

extern "C" void kernel_launch(void* const* d_in, const int* in_sizes, int n_in,
                              void* d_out, int out_size) {
    const float4* x = (const float4*)d_in[0];
    const float4* d = (const float4*)d_in[1];
    float4* y = (float4*)d_out;
    (void)in_sizes; (void)n_in; (void)out_size;

    cudaFuncSetAttribute(scan_kernel, cudaFuncAttributeMaxDynamicSharedMemorySize,
                         (int)SM_BYTES);

    init_flags_kernel<<<(NCHAIN * NSUP + 255) / 256, 256>>>();

    dim3 grid(CGRP, BATCH, NSUP);   // super on z: predecessors have smaller ids
    scan_kernel<<<grid, THREADS, SM_BYTES>>>(x, d, y);
}